// round 15
// baseline (speedup 1.0000x reference)
#include <cuda_runtime.h>
#include <cuda_bf16.h>
#include <cstdint>

// Problem constants
#define BB   64
#define TT   256
#define DIN  512
#define HH   1024
#define PP   256
#define G4H  4096
#define MROWS (TT*BB)  // 16384
#define NBLK 128

// ---------------------------------------------------------------------------
// Scratch (__device__ globals; allocation is forbidden)
// ---------------------------------------------------------------------------
__device__ float g_xg[(size_t)MROWS * G4H];                   // [T*B, 4H] unit-major cols
__device__ float g_hp[(size_t)MROWS * PP];                    // hp_all fp32
__device__ float g_wc[(size_t)G4H * HH];                      // W_comb fp32 scratch
__device__ __align__(16) __nv_bfloat16 g_Abf[(size_t)MROWS * (3 * DIN)];
__device__ __align__(16) __nv_bfloat16 g_Wbf[(size_t)G4H * (3 * DIN)];
__device__ __align__(16) __nv_bfloat16 g_Wcbf[4 * (size_t)G4H * 2048];  // Wc' [hi|lo], unit-major rows
__device__ __align__(16) __nv_bfloat16 g_Wrbf[4 * (size_t)PP * 3072];   // W_hr' [hi|lo|hi]
__device__ __align__(16) __nv_bfloat16 g_hall[(size_t)MROWS * 2048];    // h' history [hi|lo]
// distributed barrier
__device__ unsigned g_flags[NBLK * 32];
__device__ unsigned g_rel;

// ---------------------------------------------------------------------------
// Helpers
// ---------------------------------------------------------------------------
__device__ __forceinline__ uint32_t smem_u32(const void* p) {
    uint32_t a;
    asm("{ .reg .u64 t; cvta.to.shared.u64 t, %1; cvt.u32.u64 %0, t; }" : "=r"(a) : "l"(p));
    return a;
}
__device__ __forceinline__ void cp_async16(uint32_t dst, const void* src) {
    asm volatile("cp.async.cg.shared.global [%0], [%1], 16;" :: "r"(dst), "l"(src));
}
__device__ __forceinline__ void cp_commit() {
    asm volatile("cp.async.commit_group;" ::: "memory");
}
template <int N>
__device__ __forceinline__ void cp_wait() {
    asm volatile("cp.async.wait_group %0;" :: "n"(N) : "memory");
}
__device__ __forceinline__ void ldm_x4(uint32_t addr, uint32_t& r0, uint32_t& r1,
                                       uint32_t& r2, uint32_t& r3) {
    asm volatile("ldmatrix.sync.aligned.m8n8.x4.shared.b16 {%0,%1,%2,%3}, [%4];"
                 : "=r"(r0), "=r"(r1), "=r"(r2), "=r"(r3) : "r"(addr));
}
__device__ __forceinline__ void mma16816(float* d, const uint32_t* a,
                                         uint32_t b0, uint32_t b1) {
    asm volatile(
        "mma.sync.aligned.m16n8k16.row.col.f32.bf16.bf16.f32 "
        "{%0,%1,%2,%3}, {%4,%5,%6,%7}, {%8,%9}, {%0,%1,%2,%3};"
        : "+f"(d[0]), "+f"(d[1]), "+f"(d[2]), "+f"(d[3])
        : "r"(a[0]), "r"(a[1]), "r"(a[2]), "r"(a[3]), "r"(b0), "r"(b1));
}

// ---------------------------------------------------------------------------
// Distributed grid barrier (block 0 releases)
// ---------------------------------------------------------------------------
__device__ __forceinline__ void bar_sync(int j, unsigned p) {
    __syncthreads();
    __threadfence();
    if (threadIdx.x == 0)
        ((volatile unsigned*)g_flags)[j * 32] = p;
    if (j == 0) {
        if (threadIdx.x < NBLK) {
            volatile unsigned* f = ((volatile unsigned*)g_flags) + threadIdx.x * 32;
            while (*f < p) { }
        }
        __syncthreads();
        __threadfence();
        if (threadIdx.x == 0) *(volatile unsigned*)&g_rel = p;
        __syncthreads();
    } else {
        if (threadIdx.x == 0) {
            while (*(volatile unsigned*)&g_rel < p) { }
        }
        __syncthreads();
        __threadfence();
    }
}

__global__ void reset_barrier_kernel() {
    int i = threadIdx.x;
    if (i < NBLK) g_flags[i * 32] = 0;
    if (i == 0) g_rel = 0;
}

// ---------------------------------------------------------------------------
// Conversions
// ---------------------------------------------------------------------------
// A-operand: [hi|hi|lo], generic M
__global__ void conv_A_kernel(const float* __restrict__ in, __nv_bfloat16* __restrict__ out,
                              int total, int K, int remap) {
    int idx = blockIdx.x * 256 + threadIdx.x;
    if (idx >= total) return;
    int m = idx / K;
    int k = idx - m * K;
    float a = in[idx];
    int r = remap ? (((m & 255) << 6) | (m >> 8)) : m;
    __nv_bfloat16 hi = __float2bfloat16(a);
    __nv_bfloat16 lo = __float2bfloat16(a - __bfloat162float(hi));
    size_t base = (size_t)r * (3 * K);
    out[base + k] = hi;
    out[base + K + k] = hi;
    out[base + 2 * K + k] = lo;
}

// W-operand for xg GEMM: [hi|lo|hi], rows permuted to unit-major
__global__ void conv_W_kernel(const float* __restrict__ in, __nv_bfloat16* __restrict__ out,
                              int K) {
    int idx = blockIdx.x * 256 + threadIdx.x;
    if (idx >= G4H * K) return;
    int n = idx / K;
    int k = idx - n * K;
    float a = in[idx];
    __nv_bfloat16 hi = __float2bfloat16(a);
    __nv_bfloat16 lo = __float2bfloat16(a - __bfloat162float(hi));
    int np = 4 * (n & 1023) + (n >> 10);
    size_t base = (size_t)np * (3 * K);
    out[base + k] = hi;
    out[base + K + k] = lo;
    out[base + 2 * K + k] = hi;
}

// W-operand = W_hr^T for Wc prep: in [256][1024] -> out [1024][768] [hi|lo|hi]
__global__ void conv_WT_kernel(const float* __restrict__ in, __nv_bfloat16* __restrict__ out) {
    int idx = blockIdx.x * 256 + threadIdx.x;    // over 1024*256
    if (idx >= HH * PP) return;
    int n = idx >> 8, k = idx & 255;
    float a = in[k * HH + n];
    __nv_bfloat16 hi = __float2bfloat16(a);
    __nv_bfloat16 lo = __float2bfloat16(a - __bfloat162float(hi));
    size_t base = (size_t)n * 768;
    out[base + k] = hi;
    out[base + 256 + k] = lo;
    out[base + 512 + k] = hi;
}

// W_hr for proj GEMM: [256][3072] [hi|lo|hi]
__global__ void conv_Whr_kernel(const float* __restrict__ in, __nv_bfloat16* __restrict__ out) {
    int idx = blockIdx.x * 256 + threadIdx.x;    // over 256*1024
    if (idx >= PP * HH) return;
    int n = idx >> 10, k = idx & 1023;
    float a = in[idx];
    __nv_bfloat16 hi = __float2bfloat16(a);
    __nv_bfloat16 lo = __float2bfloat16(a - __bfloat162float(hi));
    size_t base = (size_t)n * 3072;
    out[base + k] = hi;
    out[base + 1024 + k] = lo;
    out[base + 2048 + k] = hi;
}

// Wc fp32 [4096][1024] -> scan layout: unit-major rows, [hi(1024)|lo(1024)]
__global__ void conv_Wc_kernel(const float* __restrict__ in, __nv_bfloat16* __restrict__ out) {
    int idx = blockIdx.x * 256 + threadIdx.x;    // over 4096*1024
    if (idx >= G4H * HH) return;
    int n = idx >> 10, k = idx & 1023;
    float a = in[idx];
    __nv_bfloat16 hi = __float2bfloat16(a);
    __nv_bfloat16 lo = __float2bfloat16(a - __bfloat162float(hi));
    int np = 4 * (n & 1023) + (n >> 10);
    out[(size_t)np * 2048 + k] = hi;
    out[(size_t)np * 2048 + 1024 + k] = lo;
}

// ---------------------------------------------------------------------------
// General mma.sync GEMM: C[m][n] = sum_k A'[m][k]*W'[n][k] (+ permuted bias)
// amap: 0 = contiguous A (ld=Ald=K3); 1 = A physical [hi|lo] (Ald=2048),
//       virtual K3=3072 mapped hi-hi-lo.
// ---------------------------------------------------------------------------
#define LDS_ROW 40
#define GTILE_BYTES (128 * LDS_ROW * 2)

__device__ __forceinline__ int amap_off(int c, int amap) {
    if (amap == 0) return c * 32;
    return (c < 32) ? c * 32 : ((c < 64) ? (c - 32) * 32 : 1024 + (c - 64) * 32);
}

__global__ __launch_bounds__(256) void gemm_mma_kernel(
    const __nv_bfloat16* __restrict__ A,
    const __nv_bfloat16* __restrict__ W,
    const float* __restrict__ b1, const float* __restrict__ b2,
    float* __restrict__ C, int K3, int Ald, int amap, int ldc, int bias_mode)
{
    __shared__ alignas(16) __nv_bfloat16 sA[2][128][LDS_ROW];
    __shared__ alignas(16) __nv_bfloat16 sB[2][128][LDS_ROW];

    const int tid  = threadIdx.x;
    const int wid  = tid >> 5;
    const int lane = tid & 31;
    const int m0 = blockIdx.y * 128;
    const int n0 = blockIdx.x * 128;
    const int wm = (wid >> 2) * 64;
    const int wn = (wid & 3) * 32;

    const uint32_t sA_u = smem_u32(sA);
    const uint32_t sB_u = smem_u32(sB);

    float acc[4][4][4];
#pragma unroll
    for (int mi = 0; mi < 4; mi++)
#pragma unroll
        for (int nj = 0; nj < 4; nj++)
#pragma unroll
            for (int e = 0; e < 4; e++) acc[mi][nj][e] = 0.f;

    const int nchunks = K3 >> 5;

    const uint32_t a_off = (uint32_t)((wm + (lane & 15)) * LDS_ROW + ((lane >> 4) * 8)) * 2;
    const uint32_t b_off = (uint32_t)((wn + ((lane >> 3) & 1) * 8 + (lane & 7)) * LDS_ROW
                                      + ((lane >> 4) * 8)) * 2;

    {
        const __nv_bfloat16* Ag = A + (size_t)m0 * Ald + amap_off(0, amap);
        const __nv_bfloat16* Wg = W + (size_t)n0 * K3;
#pragma unroll
        for (int i = 0; i < 2; i++) {
            int seg = i * 256 + tid;
            int row = seg >> 2, s = seg & 3;
            uint32_t off = (uint32_t)(row * LDS_ROW + s * 8) * 2;
            cp_async16(sA_u + off, Ag + (size_t)row * Ald + s * 8);
            cp_async16(sB_u + off, Wg + (size_t)row * K3 + s * 8);
        }
        cp_commit();
    }

    for (int c = 0; c < nchunks; c++) {
        const int buf = c & 1;
        if (c + 1 < nchunks) {
            const int nb = (c + 1) & 1;
            const __nv_bfloat16* Ag = A + (size_t)m0 * Ald + amap_off(c + 1, amap);
            const __nv_bfloat16* Wg = W + (size_t)n0 * K3 + (c + 1) * 32;
#pragma unroll
            for (int i = 0; i < 2; i++) {
                int seg = i * 256 + tid;
                int row = seg >> 2, s = seg & 3;
                uint32_t off = (uint32_t)(nb * GTILE_BYTES + (row * LDS_ROW + s * 8) * 2);
                cp_async16(sA_u + off, Ag + (size_t)row * Ald + s * 8);
                cp_async16(sB_u + off, Wg + (size_t)row * K3 + s * 8);
            }
            cp_commit();
            cp_wait<1>();
        } else {
            cp_wait<0>();
        }
        __syncthreads();

        const uint32_t abase = sA_u + buf * GTILE_BYTES;
        const uint32_t bbase = sB_u + buf * GTILE_BYTES;
#pragma unroll
        for (int ks = 0; ks < 2; ks++) {
            const uint32_t koff = (uint32_t)(ks * 16 * 2);
            uint32_t a[4][4];
#pragma unroll
            for (int mi = 0; mi < 4; mi++)
                ldm_x4(abase + a_off + koff + (uint32_t)(mi * 16 * LDS_ROW * 2),
                       a[mi][0], a[mi][1], a[mi][2], a[mi][3]);
            uint32_t bfrag[4][2];
#pragma unroll
            for (int g = 0; g < 2; g++) {
                uint32_t r0, r1, r2, r3;
                ldm_x4(bbase + b_off + koff + (uint32_t)(g * 16 * LDS_ROW * 2),
                       r0, r1, r2, r3);
                bfrag[g * 2 + 0][0] = r0; bfrag[g * 2 + 0][1] = r2;
                bfrag[g * 2 + 1][0] = r1; bfrag[g * 2 + 1][1] = r3;
            }
#pragma unroll
            for (int mi = 0; mi < 4; mi++)
#pragma unroll
                for (int nj = 0; nj < 4; nj++)
                    mma16816(acc[mi][nj], a[mi], bfrag[nj][0], bfrag[nj][1]);
        }
        __syncthreads();
    }

    float bs0[4], bs1[4];
#pragma unroll
    for (int nj = 0; nj < 4; nj++) {
        bs0[nj] = 0.f; bs1[nj] = 0.f;
        if (bias_mode) {
            int n = n0 + wn + nj * 8 + (lane & 3) * 2;
            int o0 = ((n & 3) << 10) | (n >> 2);
            int o1 = (((n + 1) & 3) << 10) | ((n + 1) >> 2);
            bs0[nj] = b1[o0] + b2[o0];
            bs1[nj] = b1[o1] + b2[o1];
        }
    }
#pragma unroll
    for (int mi = 0; mi < 4; mi++) {
        int mrow = m0 + wm + mi * 16 + (lane >> 2);
#pragma unroll
        for (int nj = 0; nj < 4; nj++) {
            int n = n0 + wn + nj * 8 + (lane & 3) * 2;
            float2 v0 = make_float2(acc[mi][nj][0] + bs0[nj], acc[mi][nj][1] + bs1[nj]);
            float2 v1 = make_float2(acc[mi][nj][2] + bs0[nj], acc[mi][nj][3] + bs1[nj]);
            *(float2*)&C[(size_t)mrow * ldc + n]       = v0;
            *(float2*)&C[(size_t)(mrow + 8) * ldc + n] = v1;
        }
    }
}

// ---------------------------------------------------------------------------
// Single-phase tensor-core LSTM scan (combined weights).
// 128 blocks x 256 threads. Block j owns 32 gate cols (units j*8..+8, 4 gates).
// Per step: gates = xg + h'(t-1) @ Wc'^T (K=1024, hi/lo split: 16 A-chunks,
// 24 mma passes), cell update local, h'(t) -> g_hall, ONE barrier.
// ---------------------------------------------------------------------------
#define CH_ROW   136
#define CH_BYTES (64 * CH_ROW * 2)     // 17408
#define WC_ROW   2056

#define OFF_WC 0
#define SZ_WC  (32 * WC_ROW * 2)       // 131584
#define OFF_ST (OFF_WC + SZ_WC)
#define SZ_ST  (4 * CH_BYTES)          // 69632
#define OFF_SH (OFF_ST + SZ_ST)
#define SZ_SH  (64 * 9 * 4)            // 2304
#define OFF_XG (OFF_SH + SZ_SH)
#define SZ_XG  (2 * 64 * 36 * 4)       // 18432
#define SCAN_SMEM (OFF_XG + SZ_XG)     // 221952

__global__ __launch_bounds__(256, 1) void lstm_scan_tc(
    const float* __restrict__ xg,
    const __nv_bfloat16* __restrict__ Wc,   // [4096][2048] unit-major rows
    __nv_bfloat16* __restrict__ hall,       // [T*64][2048]
    unsigned pbase)
{
    extern __shared__ char dsm[];
    float* sH = (float*)(dsm + OFF_SH);
    float* sXg = (float*)(dsm + OFF_XG);
    const uint32_t sWc_u = smem_u32(dsm + OFF_WC);
    const uint32_t st_u  = smem_u32(dsm + OFF_ST);
    const uint32_t sXg_u = smem_u32(dsm + OFF_XG);

    const int tid = threadIdx.x;
    const int lane = tid & 31;
    const int w = tid >> 5;
    const int j = blockIdx.x;
    const int wm = (w & 3) * 16;
    const int wn = (w >> 2) * 16;

    // persistent Wc slice [32][2048] + xg(0)
    for (int i = tid; i < 8192; i += 256) {
        int r = i >> 8, s = i & 255;
        cp_async16(sWc_u + (uint32_t)(r * WC_ROW + s * 8) * 2,
                   Wc + (size_t)(j * 32 + r) * 2048 + s * 8);
    }
    for (int k = 0; k < 2; k++) {
        int i = k * 256 + tid;
        int r = i >> 3, s = i & 7;
        cp_async16(sXg_u + (uint32_t)(r * 144 + s * 16),
                   xg + (size_t)r * G4H + j * 32 + s * 4);
    }
    cp_commit();
    cp_wait<0>();
    __syncthreads();

    float cst[4] = {0.f, 0.f, 0.f, 0.f};

    for (int t = 0; t < TT; t++) {
        float acc[2][4];
#pragma unroll
        for (int nj = 0; nj < 2; nj++)
#pragma unroll
            for (int e = 0; e < 4; e++) acc[nj][e] = 0.f;

        if (t > 0) {
            const __nv_bfloat16* hp = hall + (size_t)(t - 1) * 64 * 2048;
            // prologue: chunks 0..2
            for (int pc = 0; pc < 3; pc++) {
                int ccol = (pc < 8) ? pc * 128 : 1024 + (pc - 8) * 128;
#pragma unroll
                for (int k = 0; k < 4; k++) {
                    int i = k * 256 + tid;
                    int r = i >> 4, s = i & 15;
                    cp_async16(st_u + (uint32_t)(pc * CH_BYTES + (r * CH_ROW + s * 8) * 2),
                               hp + (size_t)r * 2048 + ccol + s * 8);
                }
                cp_commit();
            }
            for (int c = 0; c < 16; c++) {
                if (c < 14) cp_wait<2>();
                else if (c == 14) cp_wait<1>();
                else cp_wait<0>();
                __syncthreads();
                const uint32_t abase = st_u + (uint32_t)((c & 3) * CH_BYTES);
                const int wc1 = (c < 8) ? c * 128 : (c - 8) * 128;   // Whi (or Whi for Alo)
                // pass 1
#pragma unroll
                for (int ks = 0; ks < 8; ks++) {
                    uint32_t a[4], r0, r1, r2, r3;
                    ldm_x4(abase + (uint32_t)((wm + (lane & 15)) * CH_ROW
                                              + (lane >> 4) * 8 + ks * 16) * 2,
                           a[0], a[1], a[2], a[3]);
                    ldm_x4(sWc_u + (uint32_t)((wn + ((lane >> 3) & 1) * 8 + (lane & 7)) * WC_ROW
                                              + (lane >> 4) * 8 + wc1 + ks * 16) * 2,
                           r0, r1, r2, r3);
                    mma16816(acc[0], a, r0, r2);
                    mma16816(acc[1], a, r1, r3);
                }
                if (c < 8) {    // pass 2: Ahi x Wlo
                    const int wc2 = 1024 + c * 128;
#pragma unroll
                    for (int ks = 0; ks < 8; ks++) {
                        uint32_t a[4], r0, r1, r2, r3;
                        ldm_x4(abase + (uint32_t)((wm + (lane & 15)) * CH_ROW
                                                  + (lane >> 4) * 8 + ks * 16) * 2,
                               a[0], a[1], a[2], a[3]);
                        ldm_x4(sWc_u + (uint32_t)((wn + ((lane >> 3) & 1) * 8 + (lane & 7)) * WC_ROW
                                                  + (lane >> 4) * 8 + wc2 + ks * 16) * 2,
                               r0, r1, r2, r3);
                        mma16816(acc[0], a, r0, r2);
                        mma16816(acc[1], a, r1, r3);
                    }
                }
                if (c + 3 < 16) {
                    int nc = c + 3;
                    int ccol = (nc < 8) ? nc * 128 : 1024 + (nc - 8) * 128;
                    uint32_t base = st_u + (uint32_t)((nc & 3) * CH_BYTES);
#pragma unroll
                    for (int k = 0; k < 4; k++) {
                        int i = k * 256 + tid;
                        int r = i >> 4, s = i & 15;
                        cp_async16(base + (uint32_t)((r * CH_ROW + s * 8) * 2),
                                   hp + (size_t)r * 2048 + ccol + s * 8);
                    }
                    cp_commit();
                }
            }
        }

        // ---- add xg (SMEM buf t&1), cell update ----
        {
            const float* sx = sXg + (t & 1) * (64 * 36);
            int rbase = wm + (lane >> 2);
#pragma unroll
            for (int nj = 0; nj < 2; nj++) {
#pragma unroll
                for (int rp = 0; rp < 2; rp++) {
                    int row = rbase + rp * 8;
                    int cl = wn + nj * 8 + (lane & 3) * 2;
                    float2 xv = *(const float2*)&sx[row * 36 + cl];
                    float x0 = acc[nj][rp * 2 + 0] + xv.x;
                    float x1 = acc[nj][rp * 2 + 1] + xv.y;
                    float y0 = __shfl_xor_sync(0xffffffffu, x0, 1);
                    float y1 = __shfl_xor_sync(0xffffffffu, x1, 1);
                    if (!(lane & 1)) {
                        float gi = 1.f / (1.f + __expf(-x0));
                        float gf = 1.f / (1.f + __expf(-x1));
                        float gg = tanhf(y0);
                        float go = 1.f / (1.f + __expf(-y1));
                        float c = gf * cst[nj * 2 + rp] + gi * gg;
                        cst[nj * 2 + rp] = c;
                        float h = go * tanhf(c);
                        sH[row * 9 + (cl >> 2)] = h;
                    }
                }
            }
        }
        __syncthreads();

        // ---- h'(t) writeback: [hi|lo] at rows t*64.., cols j*8.. ----
        if (tid < 64) {
            __align__(16) __nv_bfloat16 hi8[8], lo8[8];
#pragma unroll
            for (int u = 0; u < 8; u++) {
                float hv = sH[tid * 9 + u];
                hi8[u] = __float2bfloat16(hv);
                lo8[u] = __float2bfloat16(hv - __bfloat162float(hi8[u]));
            }
            __nv_bfloat16* dst = hall + (size_t)(t * 64 + tid) * 2048 + j * 8;
            __stcg((uint4*)dst,          *(const uint4*)hi8);
            __stcg((uint4*)(dst + 1024), *(const uint4*)lo8);
        }

        // prefetch xg(t+1) (completes under next gate phase's waits)
        if (t + 1 < TT) {
#pragma unroll
            for (int k = 0; k < 2; k++) {
                int i = k * 256 + tid;
                int r = i >> 3, s = i & 7;
                cp_async16(sXg_u + (uint32_t)(((t + 1) & 1) * (64 * 144) + r * 144 + s * 16),
                           xg + (size_t)((t + 1) * 64 + r) * G4H + j * 32 + s * 4);
            }
            cp_commit();
            if (t + 1 == TT - 1) { }  // fine: drained by next phase waits
        }
        if (t == TT - 1) { cp_wait<0>(); }

        bar_sync(j, pbase + t + 1);
        if (t + 1 < TT && (t + 1) == 0) { }  // no-op
        // ensure xg(t+1) ready when next step skips gate phase (only t=0 case, handled in prologue)
    }
}

// ---------------------------------------------------------------------------
// Launch
// ---------------------------------------------------------------------------
extern "C" void kernel_launch(void* const* d_in, const int* in_sizes, int n_in,
                              void* d_out, int out_size)
{
    const float* x     = (const float*)d_in[0];
    const float* W_ih0 = (const float*)d_in[1];
    const float* W_hh0 = (const float*)d_in[2];
    const float* b_ih0 = (const float*)d_in[3];
    const float* b_hh0 = (const float*)d_in[4];
    const float* W_hr0 = (const float*)d_in[5];
    const float* W_ihs = (const float*)d_in[6];
    const float* W_hhs = (const float*)d_in[7];
    const float* b_ihs = (const float*)d_in[8];
    const float* b_hhs = (const float*)d_in[9];
    const float* W_hrs = (const float*)d_in[10];

    float *xg, *hp, *wc;
    __nv_bfloat16 *Abf, *Wbf, *Wcbf, *Wrbf, *hall;
    cudaGetSymbolAddress((void**)&xg,   g_xg);
    cudaGetSymbolAddress((void**)&hp,   g_hp);
    cudaGetSymbolAddress((void**)&wc,   g_wc);
    cudaGetSymbolAddress((void**)&Abf,  g_Abf);
    cudaGetSymbolAddress((void**)&Wbf,  g_Wbf);
    cudaGetSymbolAddress((void**)&Wcbf, g_Wcbf);
    cudaGetSymbolAddress((void**)&Wrbf, g_Wrbf);
    cudaGetSymbolAddress((void**)&hall, g_hall);

    cudaFuncSetAttribute(lstm_scan_tc,
                         cudaFuncAttributeMaxDynamicSharedMemorySize, SCAN_SMEM);

    reset_barrier_kernel<<<1, 256>>>();

    // ---- weight prep per layer: Wc = W_hh @ W_hr (split-bf16 GEMM) + W_hr' ----
    for (int l = 0; l < 4; l++) {
        const float* Whh = (l == 0) ? W_hh0 : W_hhs + (size_t)(l - 1) * G4H * PP;
        const float* Whr = (l == 0) ? W_hr0 : W_hrs + (size_t)(l - 1) * PP * HH;
        conv_A_kernel<<<(G4H * PP) / 256, 256>>>(Whh, Abf, G4H * PP, PP, 0);
        conv_WT_kernel<<<(HH * PP) / 256, 256>>>(Whr, Wbf);
        gemm_mma_kernel<<<dim3(8, 32), 256>>>(Abf, Wbf, nullptr, nullptr,
                                              wc, 768, 768, 0, HH, 0);
        conv_Wc_kernel<<<(G4H * HH) / 256, 256>>>(wc, Wcbf + (size_t)l * G4H * 2048);
        conv_Whr_kernel<<<(PP * HH) / 256, 256>>>(Whr, Wrbf + (size_t)l * PP * 3072);
    }

    // ---- layer 0 xg ----
    conv_W_kernel<<<(G4H * DIN) / 256, 256>>>(W_ih0, Wbf, DIN);
    conv_A_kernel<<<(MROWS * DIN) / 256, 256>>>(x, Abf, MROWS * DIN, DIN, 1);
    gemm_mma_kernel<<<dim3(32, 128), 256>>>(Abf, Wbf, b_ih0, b_hh0,
                                            xg, 1536, 1536, 0, G4H, 1);

    for (int l = 0; l < 4; l++) {
        lstm_scan_tc<<<NBLK, 256, SCAN_SMEM>>>(xg, Wcbf + (size_t)l * G4H * 2048,
                                               hall, (unsigned)(l * TT));
        // hp_all = h_all @ W_hr^T
        gemm_mma_kernel<<<dim3(2, 128), 256>>>(hall, Wrbf + (size_t)l * PP * 3072,
                                               nullptr, nullptr, hp, 3072, 2048, 1, PP, 0);
        if (l < 3) {
            conv_W_kernel<<<(G4H * PP) / 256, 256>>>(W_ihs + (size_t)l * G4H * PP, Wbf, PP);
            conv_A_kernel<<<(MROWS * PP) / 256, 256>>>(hp, Abf, MROWS * PP, PP, 0);
            gemm_mma_kernel<<<dim3(32, 128), 256>>>(Abf, Wbf,
                                                    b_ihs + (size_t)l * G4H,
                                                    b_hhs + (size_t)l * G4H,
                                                    xg, 768, 768, 0, G4H, 1);
        }
    }

    // output = hp of last timestep, last layer
    cudaMemcpyAsync(d_out, hp + (size_t)(TT - 1) * BB * PP,
                    (size_t)BB * PP * sizeof(float),
                    cudaMemcpyDeviceToDevice);
    (void)in_sizes; (void)n_in; (void)out_size;
}

// round 16
// speedup vs baseline: 1.2827x; 1.2827x over previous
#include <cuda_runtime.h>
#include <cuda_bf16.h>
#include <cstdint>

// Problem constants
#define BB   64
#define TT   256
#define DIN  512
#define HH   1024
#define PP   256
#define G4H  4096
#define MROWS (TT*BB)  // 16384
#define NBLK 128

// ---------------------------------------------------------------------------
// Scratch (__device__ globals; allocation is forbidden)
// ---------------------------------------------------------------------------
__device__ float g_xg[(size_t)MROWS * G4H];                 // [T*B, 4H] unit-major cols
__device__ float g_hp[(size_t)MROWS * PP];                  // hp_all fp32 (layer output)
__device__ __align__(16) __nv_bfloat16 g_Abf[(size_t)MROWS * (3 * DIN)];
__device__ __align__(16) __nv_bfloat16 g_Wbf[(size_t)G4H * (3 * DIN)];
__device__ __align__(16) __nv_bfloat16 g_Wgbf[4 * (size_t)G4H * 768];   // [4096][768] unit-major rows
__device__ __align__(16) __nv_bfloat16 g_Wrbf[4 * (size_t)PP * 3072];   // [256][3072]
__device__ __align__(16) __nv_bfloat16 g_hpbf[2][BB * 512];             // hp' [hi|lo], double-buffered
__device__ __align__(16) __nv_bfloat16 g_hbf[2][BB * 2048];             // h'  [hi|lo], double-buffered
__device__ float g_pp[2][4][BB][PP];                                    // proj split-K partials
// producer-consumer flags (one per 128B line)
__device__ unsigned g_fA[NBLK * 32];
__device__ unsigned g_fB[NBLK * 32];
__device__ unsigned g_fC[32 * 32];

// ---------------------------------------------------------------------------
// Helpers
// ---------------------------------------------------------------------------
__device__ __forceinline__ uint32_t smem_u32(const void* p) {
    uint32_t a;
    asm("{ .reg .u64 t; cvta.to.shared.u64 t, %1; cvt.u32.u64 %0, t; }" : "=r"(a) : "l"(p));
    return a;
}
__device__ __forceinline__ void cp_async16(uint32_t dst, const void* src) {
    asm volatile("cp.async.cg.shared.global [%0], [%1], 16;" :: "r"(dst), "l"(src));
}
__device__ __forceinline__ void cp_commit() {
    asm volatile("cp.async.commit_group;" ::: "memory");
}
template <int N>
__device__ __forceinline__ void cp_wait() {
    asm volatile("cp.async.wait_group %0;" :: "n"(N) : "memory");
}
__device__ __forceinline__ void ldm_x4(uint32_t addr, uint32_t& r0, uint32_t& r1,
                                       uint32_t& r2, uint32_t& r3) {
    asm volatile("ldmatrix.sync.aligned.m8n8.x4.shared.b16 {%0,%1,%2,%3}, [%4];"
                 : "=r"(r0), "=r"(r1), "=r"(r2), "=r"(r3) : "r"(addr));
}
__device__ __forceinline__ void ldm_x2(uint32_t addr, uint32_t& r0, uint32_t& r1) {
    asm volatile("ldmatrix.sync.aligned.m8n8.x2.shared.b16 {%0,%1}, [%2];"
                 : "=r"(r0), "=r"(r1) : "r"(addr));
}
__device__ __forceinline__ void mma16816(float* d, const uint32_t* a,
                                         uint32_t b0, uint32_t b1) {
    asm volatile(
        "mma.sync.aligned.m16n8k16.row.col.f32.bf16.bf16.f32 "
        "{%0,%1,%2,%3}, {%4,%5,%6,%7}, {%8,%9}, {%0,%1,%2,%3};"
        : "+f"(d[0]), "+f"(d[1]), "+f"(d[2]), "+f"(d[3])
        : "r"(a[0]), "r"(a[1]), "r"(a[2]), "r"(a[3]), "r"(b0), "r"(b1));
}
__device__ __forceinline__ void poll_ge(volatile unsigned* f, unsigned p) {
    while (*f < p) { }
}

__global__ void reset_flags_kernel() {
    int i = threadIdx.x;
    if (i < NBLK) { g_fA[i * 32] = 0; g_fB[i * 32] = 0; }
    if (i < 32)   { g_fC[i * 32] = 0; }
}

// ---------------------------------------------------------------------------
// Conversions (unchanged from R13)
// ---------------------------------------------------------------------------
__global__ void conv_A_kernel(const float* __restrict__ in, __nv_bfloat16* __restrict__ out,
                              int K, int remap) {
    int idx = blockIdx.x * 256 + threadIdx.x;
    if (idx >= MROWS * K) return;
    int m = idx / K;
    int k = idx - m * K;
    float a = in[idx];
    int r = remap ? (((m & 255) << 6) | (m >> 8)) : m;   // (b,t) -> row t*64+b
    __nv_bfloat16 hi = __float2bfloat16(a);
    __nv_bfloat16 lo = __float2bfloat16(a - __bfloat162float(hi));
    size_t base = (size_t)r * (3 * K);
    out[base + k] = hi;
    out[base + K + k] = hi;
    out[base + 2 * K + k] = lo;
}

__global__ void conv_W_kernel(const float* __restrict__ in, __nv_bfloat16* __restrict__ out,
                              int K) {
    int idx = blockIdx.x * 256 + threadIdx.x;
    if (idx >= G4H * K) return;
    int n = idx / K;
    int k = idx - n * K;
    float a = in[idx];
    __nv_bfloat16 hi = __float2bfloat16(a);
    __nv_bfloat16 lo = __float2bfloat16(a - __bfloat162float(hi));
    int np = 4 * (n & 1023) + (n >> 10);     // gate-major -> unit-major rows
    size_t base = (size_t)np * (3 * K);
    out[base + k] = hi;
    out[base + K + k] = lo;
    out[base + 2 * K + k] = hi;
}

__global__ void conv_Whh_kernel(const float* __restrict__ in, __nv_bfloat16* __restrict__ out) {
    int idx = blockIdx.x * 256 + threadIdx.x;
    if (idx >= G4H * PP) return;
    int n = idx >> 8, k = idx & 255;
    float a = in[idx];
    __nv_bfloat16 hi = __float2bfloat16(a);
    __nv_bfloat16 lo = __float2bfloat16(a - __bfloat162float(hi));
    int np = 4 * (n & 1023) + (n >> 10);
    size_t base = (size_t)np * 768;
    out[base + k] = hi;          // [Whi | Wlo | Whi]
    out[base + 256 + k] = lo;
    out[base + 512 + k] = hi;
}
__global__ void conv_Whr_kernel(const float* __restrict__ in, __nv_bfloat16* __restrict__ out) {
    int idx = blockIdx.x * 256 + threadIdx.x;
    if (idx >= PP * HH) return;
    int n = idx >> 10, k = idx & 1023;
    float a = in[idx];
    __nv_bfloat16 hi = __float2bfloat16(a);
    __nv_bfloat16 lo = __float2bfloat16(a - __bfloat162float(hi));
    size_t base = (size_t)n * 3072;
    out[base + k] = hi;          // [Whi | Wlo | Whi]
    out[base + 1024 + k] = lo;
    out[base + 2048 + k] = hi;
}

// ---------------------------------------------------------------------------
// Input-projection GEMM via mma.sync (unchanged from R13)
// ---------------------------------------------------------------------------
#define LDS_ROW 40
#define GTILE_BYTES (128 * LDS_ROW * 2)

__global__ __launch_bounds__(256) void gemm_mma_kernel(
    const __nv_bfloat16* __restrict__ A,
    const __nv_bfloat16* __restrict__ W,
    const float* __restrict__ b1, const float* __restrict__ b2,
    float* __restrict__ C, int K3)
{
    __shared__ alignas(16) __nv_bfloat16 sA[2][128][LDS_ROW];
    __shared__ alignas(16) __nv_bfloat16 sB[2][128][LDS_ROW];

    const int tid  = threadIdx.x;
    const int wid  = tid >> 5;
    const int lane = tid & 31;
    const int m0 = blockIdx.y * 128;
    const int n0 = blockIdx.x * 128;
    const int wm = (wid >> 2) * 64;
    const int wn = (wid & 3) * 32;

    const uint32_t sA_u = smem_u32(sA);
    const uint32_t sB_u = smem_u32(sB);

    float acc[4][4][4];
#pragma unroll
    for (int mi = 0; mi < 4; mi++)
#pragma unroll
        for (int nj = 0; nj < 4; nj++)
#pragma unroll
            for (int e = 0; e < 4; e++) acc[mi][nj][e] = 0.f;

    const int nchunks = K3 >> 5;

    const uint32_t a_off = (uint32_t)((wm + (lane & 15)) * LDS_ROW + ((lane >> 4) * 8)) * 2;
    const uint32_t b_off = (uint32_t)((wn + ((lane >> 3) & 1) * 8 + (lane & 7)) * LDS_ROW
                                      + ((lane >> 4) * 8)) * 2;

    {
        const __nv_bfloat16* Ag = A + (size_t)m0 * K3;
        const __nv_bfloat16* Wg = W + (size_t)n0 * K3;
#pragma unroll
        for (int i = 0; i < 2; i++) {
            int seg = i * 256 + tid;
            int row = seg >> 2, s = seg & 3;
            uint32_t off = (uint32_t)(row * LDS_ROW + s * 8) * 2;
            cp_async16(sA_u + off, Ag + (size_t)row * K3 + s * 8);
            cp_async16(sB_u + off, Wg + (size_t)row * K3 + s * 8);
        }
        cp_commit();
    }

    for (int c = 0; c < nchunks; c++) {
        const int buf = c & 1;
        if (c + 1 < nchunks) {
            const int nb = (c + 1) & 1;
            const __nv_bfloat16* Ag = A + (size_t)m0 * K3 + (c + 1) * 32;
            const __nv_bfloat16* Wg = W + (size_t)n0 * K3 + (c + 1) * 32;
#pragma unroll
            for (int i = 0; i < 2; i++) {
                int seg = i * 256 + tid;
                int row = seg >> 2, s = seg & 3;
                uint32_t off = (uint32_t)(nb * GTILE_BYTES + (row * LDS_ROW + s * 8) * 2);
                cp_async16(sA_u + off, Ag + (size_t)row * K3 + s * 8);
                cp_async16(sB_u + off, Wg + (size_t)row * K3 + s * 8);
            }
            cp_commit();
            cp_wait<1>();
        } else {
            cp_wait<0>();
        }
        __syncthreads();

        const uint32_t abase = sA_u + buf * GTILE_BYTES;
        const uint32_t bbase = sB_u + buf * GTILE_BYTES;
#pragma unroll
        for (int ks = 0; ks < 2; ks++) {
            const uint32_t koff = (uint32_t)(ks * 16 * 2);
            uint32_t a[4][4];
#pragma unroll
            for (int mi = 0; mi < 4; mi++)
                ldm_x4(abase + a_off + koff + (uint32_t)(mi * 16 * LDS_ROW * 2),
                       a[mi][0], a[mi][1], a[mi][2], a[mi][3]);
            uint32_t bfrag[4][2];
#pragma unroll
            for (int g = 0; g < 2; g++) {
                uint32_t r0, r1, r2, r3;
                ldm_x4(bbase + b_off + koff + (uint32_t)(g * 16 * LDS_ROW * 2),
                       r0, r1, r2, r3);
                bfrag[g * 2 + 0][0] = r0; bfrag[g * 2 + 0][1] = r2;
                bfrag[g * 2 + 1][0] = r1; bfrag[g * 2 + 1][1] = r3;
            }
#pragma unroll
            for (int mi = 0; mi < 4; mi++)
#pragma unroll
                for (int nj = 0; nj < 4; nj++)
                    mma16816(acc[mi][nj], a[mi], bfrag[nj][0], bfrag[nj][1]);
        }
        __syncthreads();
    }

    float bs0[4], bs1[4];
#pragma unroll
    for (int nj = 0; nj < 4; nj++) {
        int n = n0 + wn + nj * 8 + (lane & 3) * 2;
        int o0 = ((n & 3) << 10) | (n >> 2);
        int o1 = (((n + 1) & 3) << 10) | ((n + 1) >> 2);
        bs0[nj] = b1[o0] + b2[o0];
        bs1[nj] = b1[o1] + b2[o1];
    }
#pragma unroll
    for (int mi = 0; mi < 4; mi++) {
        int mrow = m0 + wm + mi * 16 + (lane >> 2);
#pragma unroll
        for (int nj = 0; nj < 4; nj++) {
            int n = n0 + wn + nj * 8 + (lane & 3) * 2;
            float2 v0 = make_float2(acc[mi][nj][0] + bs0[nj], acc[mi][nj][1] + bs1[nj]);
            float2 v1 = make_float2(acc[mi][nj][2] + bs0[nj], acc[mi][nj][3] + bs1[nj]);
            *(float2*)&C[(size_t)mrow * G4H + n]       = v0;
            *(float2*)&C[(size_t)(mrow + 8) * G4H + n] = v1;
        }
    }
}

// ---------------------------------------------------------------------------
// Tensor-core persistent LSTM scan, v4: producer-consumer flag sync.
// 128 blocks x 256 threads. Block j: gate cols j*32..+32 (units j*8..+8).
// Proj split-K4: N-group g=j&31, K-quarter q=j>>5. Reduce on blocks j<32
// (cols j*8..+8) after waiting its 4 K-quarter partners.
// Flags: fA[j] = h'(t) written; fB[j] = partial(t) written; fC[g] = hp'(t)
// written. Monotone counters (pbase + t + 1); buffers double-buffered on t&1.
// ---------------------------------------------------------------------------
#define CH_ROW   136
#define CH_BYTES (64 * CH_ROW * 2)     // 17408

#define OFF_WG 0
#define SZ_WG  (32 * 776 * 2)          // 49664
#define OFF_WR (OFF_WG + SZ_WG)
#define SZ_WR  (8 * 3080 * 2)          // 49280
#define OFF_ST (OFF_WR + SZ_WR)
#define SZ_ST  (4 * CH_BYTES)          // 69632
#define OFF_SH (OFF_ST + SZ_ST)
#define SZ_SH  (64 * 9 * 4)            // 2304
#define OFF_XG (OFF_SH + SZ_SH)
#define SZ_XG  (2 * 64 * 36 * 4)       // 18432
#define SCAN_SMEM (OFF_XG + SZ_XG)     // 189312

__global__ __launch_bounds__(256, 1) void lstm_scan_tc(
    const float* __restrict__ xg,
    const __nv_bfloat16* __restrict__ Wg,
    const __nv_bfloat16* __restrict__ Wr,
    float* __restrict__ hp_out,
    unsigned pbase)
{
    extern __shared__ char dsm[];
    float* sH = (float*)(dsm + OFF_SH);
    float* sXg = (float*)(dsm + OFF_XG);
    const uint32_t sWg_u = smem_u32(dsm + OFF_WG);
    const uint32_t sWr_u = smem_u32(dsm + OFF_WR);
    const uint32_t st_u  = smem_u32(dsm + OFF_ST);
    const uint32_t sXg_u = smem_u32(dsm + OFF_XG);

    const int tid = threadIdx.x;
    const int lane = tid & 31;
    const int w = tid >> 5;
    const int j = blockIdx.x;
    const int g = j & 31;
    const int q = j >> 5;
    const int wq = q * 256;
    const int wm = (w & 3) * 16;
    const int wn = (w >> 2) * 16;

    // persistent weight slices + xg(0)
    for (int i = tid; i < 3072; i += 256) {            // Wg: 32 rows x 96 segs
        int r = i / 96, s = i % 96;
        cp_async16(sWg_u + (uint32_t)(r * 776 + s * 8) * 2,
                   Wg + (size_t)(j * 32 + r) * 768 + s * 8);
    }
    for (int i = tid; i < 3072; i += 256) {            // Wr: 8 rows x 384 segs
        int r = i / 384, s = i % 384;
        cp_async16(sWr_u + (uint32_t)(r * 3080 + s * 8) * 2,
                   Wr + (size_t)(g * 8 + r) * 3072 + s * 8);
    }
    for (int k = 0; k < 2; k++) {
        int i = k * 256 + tid;
        int r = i >> 3, s = i & 7;
        cp_async16(sXg_u + (uint32_t)(r * 144 + s * 16),
                   xg + (size_t)r * G4H + j * 32 + s * 4);
    }
    cp_commit();
    cp_wait<0>();
    __syncthreads();

    float cst[4] = {0.f, 0.f, 0.f, 0.f};

    for (int t = 0; t < TT; t++) {
        const int par = t & 1;
        float acc[2][4];
#pragma unroll
        for (int nj = 0; nj < 2; nj++)
#pragma unroll
            for (int e = 0; e < 4; e++) acc[nj][e] = 0.f;

        // ================= gate phase =================
        if (t > 0) {
            // wait hp'(t-1) complete (32 flagC)
            if (tid < 32) poll_ge((volatile unsigned*)&g_fC[tid * 32], pbase + t);
            __syncthreads();
            __threadfence();
            const __nv_bfloat16* hp = g_hpbf[(t - 1) & 1];
#pragma unroll
            for (int a = 0; a < 4; a++) {
#pragma unroll
                for (int k = 0; k < 4; k++) {
                    int i = k * 256 + tid;
                    int r = i >> 4, s = i & 15;
                    cp_async16(st_u + (uint32_t)(a * CH_BYTES + (r * CH_ROW + s * 8) * 2),
                               hp + (size_t)r * 512 + a * 128 + s * 8);
                }
                cp_commit();
            }
#pragma unroll
            for (int p = 0; p < 6; p++) {
                if (p == 0)      { cp_wait<3>(); __syncthreads(); }
                else if (p == 1) { cp_wait<2>(); __syncthreads(); }
                else if (p == 4) { cp_wait<0>(); __syncthreads(); }
                const int sl = (p < 4) ? (p & 1) : (p - 2);
                const uint32_t abase = st_u + (uint32_t)(sl * CH_BYTES);
                const int wb = p * 128;
#pragma unroll
                for (int ks = 0; ks < 8; ks++) {
                    uint32_t a[4], r0, r1, r2, r3;
                    ldm_x4(abase + (uint32_t)((wm + (lane & 15)) * CH_ROW
                                              + (lane >> 4) * 8 + ks * 16) * 2,
                           a[0], a[1], a[2], a[3]);
                    ldm_x4(sWg_u + (uint32_t)((wn + ((lane >> 3) & 1) * 8 + (lane & 7)) * 776
                                              + (lane >> 4) * 8 + wb + ks * 16) * 2,
                           r0, r1, r2, r3);
                    mma16816(acc[0], a, r0, r2);
                    mma16816(acc[1], a, r1, r3);
                }
            }
        }

        // ---- add xg (SMEM buf t&1), cell update ----
        {
            const float* sx = sXg + par * (64 * 36);
            int rbase = wm + (lane >> 2);
#pragma unroll
            for (int nj = 0; nj < 2; nj++) {
#pragma unroll
                for (int rp = 0; rp < 2; rp++) {
                    int row = rbase + rp * 8;
                    int cl = wn + nj * 8 + (lane & 3) * 2;
                    float2 xv = *(const float2*)&sx[row * 36 + cl];
                    float x0 = acc[nj][rp * 2 + 0] + xv.x;
                    float x1 = acc[nj][rp * 2 + 1] + xv.y;
                    float y0 = __shfl_xor_sync(0xffffffffu, x0, 1);
                    float y1 = __shfl_xor_sync(0xffffffffu, x1, 1);
                    if (!(lane & 1)) {
                        float gi = 1.f / (1.f + __expf(-x0));
                        float gf = 1.f / (1.f + __expf(-x1));
                        float gg = tanhf(y0);
                        float go = 1.f / (1.f + __expf(-y1));
                        float c = gf * cst[nj * 2 + rp] + gi * gg;
                        cst[nj * 2 + rp] = c;
                        float h = go * tanhf(c);
                        sH[row * 9 + (cl >> 2)] = h;
                    }
                }
            }
        }
        __syncthreads();

        // ---- h'(t) writeback to double buffer ----
        if (tid < 64) {
            __align__(16) __nv_bfloat16 hi8[8], lo8[8];
#pragma unroll
            for (int u = 0; u < 8; u++) {
                float hv = sH[tid * 9 + u];
                hi8[u] = __float2bfloat16(hv);
                lo8[u] = __float2bfloat16(hv - __bfloat162float(hi8[u]));
            }
            __nv_bfloat16* dst = g_hbf[par] + (size_t)tid * 2048 + j * 8;
            __stcg((uint4*)dst,          *(const uint4*)hi8);
            __stcg((uint4*)(dst + 1024), *(const uint4*)lo8);
        }
        __syncthreads();
        __threadfence();
        if (tid == 0)
            *(volatile unsigned*)&g_fA[j * 32] = pbase + t + 1;

        // ================= projection phase (split-K4) =================
        {
            // wait h'(t) quarter q: producers q*32 .. q*32+31
            if (tid < 32)
                poll_ge((volatile unsigned*)&g_fA[(q * 32 + tid) * 32], pbase + t + 1);
            __syncthreads();
            __threadfence();

            // bundle xg(t+1) prefetch with chunk 0
            if (t + 1 < TT) {
#pragma unroll
                for (int k = 0; k < 2; k++) {
                    int i = k * 256 + tid;
                    int r = i >> 3, s = i & 7;
                    cp_async16(sXg_u + (uint32_t)(((t + 1) & 1) * (64 * 144) + r * 144 + s * 16),
                               xg + (size_t)((t + 1) * 64 + r) * G4H + j * 32 + s * 4);
                }
            }
            const __nv_bfloat16* hb = g_hbf[par];
            const int cb[4] = {wq, wq + 128, 1024 + wq, 1024 + wq + 128};
#pragma unroll
            for (int a = 0; a < 4; a++) {
#pragma unroll
                for (int k = 0; k < 4; k++) {
                    int i = k * 256 + tid;
                    int r = i >> 4, s = i & 15;
                    cp_async16(st_u + (uint32_t)(a * CH_BYTES + (r * CH_ROW + s * 8) * 2),
                               hb + (size_t)r * 2048 + cb[a] + s * 8);
                }
                cp_commit();
            }

            float accP[4] = {0.f, 0.f, 0.f, 0.f};
            const int wb[6] = {wq, wq + 128, 1024 + wq, 1024 + wq + 128,
                               2048 + wq, 2048 + wq + 128};
#pragma unroll
            for (int p = 0; p < 6; p++) {
                if (p == 0)      { cp_wait<3>(); __syncthreads(); }
                else if (p == 1) { cp_wait<2>(); __syncthreads(); }
                else if (p == 4) { cp_wait<0>(); __syncthreads(); }
                if (w < 4) {
                    const int sl = (p < 4) ? (p & 1) : (p - 2);
                    const uint32_t abase = st_u + (uint32_t)(sl * CH_BYTES);
#pragma unroll
                    for (int ks = 0; ks < 8; ks++) {
                        uint32_t a[4], b0, b1;
                        ldm_x4(abase + (uint32_t)((w * 16 + (lane & 15)) * CH_ROW
                                                  + (lane >> 4) * 8 + ks * 16) * 2,
                               a[0], a[1], a[2], a[3]);
                        ldm_x2(sWr_u + (uint32_t)((lane & 7) * 3080 + ((lane >> 3) & 1) * 8
                                                  + wb[p] + ks * 16) * 2,
                               b0, b1);
                        mma16816(accP, a, b0, b1);
                    }
                }
            }
            if (w < 4) {
                int row = w * 16 + (lane >> 2);
                int col = g * 8 + (lane & 3) * 2;
                float* pp = &g_pp[par][q][0][0];
                *(float2*)&pp[row * 256 + col]       = make_float2(accP[0], accP[1]);
                *(float2*)&pp[(row + 8) * 256 + col] = make_float2(accP[2], accP[3]);
            }
        }
        __syncthreads();
        __threadfence();
        if (tid == 0)
            *(volatile unsigned*)&g_fB[j * 32] = pbase + t + 1;

        // ================= reduce (blocks j<32 only) =================
        if (j < 32) {
            if (tid < 4)
                poll_ge((volatile unsigned*)&g_fB[(j + tid * 32) * 32], pbase + t + 1);
            __syncthreads();
            __threadfence();

            int r = tid >> 2;              // 0..63
            int c2 = (tid & 3) * 2;        // 0,2,4,6
            int col = j * 8 + c2;
            float2 s0 = *(const float2*)&g_pp[par][0][r][col];
            float2 s1 = *(const float2*)&g_pp[par][1][r][col];
            float2 s2 = *(const float2*)&g_pp[par][2][r][col];
            float2 s3 = *(const float2*)&g_pp[par][3][r][col];
            float sx = s0.x + s1.x + s2.x + s3.x;
            float sy = s0.y + s1.y + s2.y + s3.y;

            // hp' [hi|lo] to double buffer (recurrence-critical)
            __nv_bfloat16 hx = __float2bfloat16(sx);
            __nv_bfloat16 hy = __float2bfloat16(sy);
            __nv_bfloat16 lx = __float2bfloat16(sx - __bfloat162float(hx));
            __nv_bfloat16 ly = __float2bfloat16(sy - __bfloat162float(hy));
            __nv_bfloat162 hp2; hp2.x = hx; hp2.y = hy;
            __nv_bfloat162 lp2; lp2.x = lx; lp2.y = ly;
            __nv_bfloat16* hpb = g_hpbf[par];
            __stcg((uint32_t*)&hpb[r * 512 + col],       *(uint32_t*)&hp2);
            __stcg((uint32_t*)&hpb[r * 512 + 256 + col], *(uint32_t*)&lp2);
            // hp fp32 (layer output)
            __stcg((float2*)&hp_out[((size_t)t * 64 + r) * PP + col],
                   make_float2(sx, sy));

            __syncthreads();
            __threadfence();
            if (tid == 0)
                *(volatile unsigned*)&g_fC[j * 32] = pbase + t + 1;
        }
    }
}

// ---------------------------------------------------------------------------
// Launch
// ---------------------------------------------------------------------------
extern "C" void kernel_launch(void* const* d_in, const int* in_sizes, int n_in,
                              void* d_out, int out_size)
{
    const float* x     = (const float*)d_in[0];
    const float* W_ih0 = (const float*)d_in[1];
    const float* W_hh0 = (const float*)d_in[2];
    const float* b_ih0 = (const float*)d_in[3];
    const float* b_hh0 = (const float*)d_in[4];
    const float* W_hr0 = (const float*)d_in[5];
    const float* W_ihs = (const float*)d_in[6];
    const float* W_hhs = (const float*)d_in[7];
    const float* b_ihs = (const float*)d_in[8];
    const float* b_hhs = (const float*)d_in[9];
    const float* W_hrs = (const float*)d_in[10];

    float *xg, *hp;
    __nv_bfloat16 *Abf, *Wbf, *Wgbf, *Wrbf;
    cudaGetSymbolAddress((void**)&xg,   g_xg);
    cudaGetSymbolAddress((void**)&hp,   g_hp);
    cudaGetSymbolAddress((void**)&Abf,  g_Abf);
    cudaGetSymbolAddress((void**)&Wbf,  g_Wbf);
    cudaGetSymbolAddress((void**)&Wgbf, g_Wgbf);
    cudaGetSymbolAddress((void**)&Wrbf, g_Wrbf);

    cudaFuncSetAttribute(lstm_scan_tc,
                         cudaFuncAttributeMaxDynamicSharedMemorySize, SCAN_SMEM);

    dim3 ggrid(32, 128);   // N/128, M/128

    reset_flags_kernel<<<1, 256>>>();

    // scan weight conversions (all layers)
    conv_Whh_kernel<<<(G4H * PP) / 256, 256>>>(W_hh0, Wgbf);
    conv_Whr_kernel<<<(PP * HH) / 256, 256>>>(W_hr0, Wrbf);
    for (int l = 0; l < 3; l++) {
        conv_Whh_kernel<<<(G4H * PP) / 256, 256>>>(
            W_hhs + (size_t)l * G4H * PP, Wgbf + (size_t)(l + 1) * G4H * 768);
        conv_Whr_kernel<<<(PP * HH) / 256, 256>>>(
            W_hrs + (size_t)l * PP * HH, Wrbf + (size_t)(l + 1) * PP * 3072);
    }

    // ---- layer 0 ----
    conv_W_kernel<<<(G4H * DIN) / 256, 256>>>(W_ih0, Wbf, DIN);
    conv_A_kernel<<<(MROWS * DIN) / 256, 256>>>(x, Abf, DIN, 1);
    gemm_mma_kernel<<<ggrid, 256>>>(Abf, Wbf, b_ih0, b_hh0, xg, 3 * DIN);
    lstm_scan_tc<<<NBLK, 256, SCAN_SMEM>>>(xg, Wgbf, Wrbf, hp, 0u);

    // ---- layers 1..3 ----
    for (int l = 0; l < 3; l++) {
        conv_W_kernel<<<(G4H * PP) / 256, 256>>>(W_ihs + (size_t)l * G4H * PP, Wbf, PP);
        conv_A_kernel<<<(MROWS * PP) / 256, 256>>>(hp, Abf, PP, 0);
        gemm_mma_kernel<<<ggrid, 256>>>(Abf, Wbf,
                                        b_ihs + (size_t)l * G4H,
                                        b_hhs + (size_t)l * G4H,
                                        xg, 3 * PP);
        lstm_scan_tc<<<NBLK, 256, SCAN_SMEM>>>(xg,
                                               Wgbf + (size_t)(l + 1) * G4H * 768,
                                               Wrbf + (size_t)(l + 1) * PP * 3072,
                                               hp, (unsigned)((l + 1) * TT));
    }

    // output = hp of last timestep, last layer
    cudaMemcpyAsync(d_out, hp + (size_t)(TT - 1) * BB * PP,
                    (size_t)BB * PP * sizeof(float),
                    cudaMemcpyDeviceToDevice);
    (void)in_sizes; (void)n_in; (void)out_size;
}

// round 17
// speedup vs baseline: 1.2837x; 1.0008x over previous
#include <cuda_runtime.h>
#include <cuda_bf16.h>
#include <cstdint>

// Problem constants
#define BB   64
#define TT   256
#define DIN  512
#define HH   1024
#define PP   256
#define G4H  4096
#define MROWS (TT*BB)  // 16384
#define NBLK 128

// ---------------------------------------------------------------------------
// Scratch (__device__ globals; allocation is forbidden)
// ---------------------------------------------------------------------------
__device__ float g_xg[(size_t)MROWS * G4H];                 // [T*B, 4H] unit-major cols
__device__ float g_hp[(size_t)MROWS * PP];                  // hp_all fp32 (layer output)
__device__ __align__(16) __nv_bfloat16 g_Abf[(size_t)MROWS * (3 * DIN)];
__device__ __align__(16) __nv_bfloat16 g_Wbf[(size_t)G4H * (3 * DIN)];
__device__ __align__(16) __nv_bfloat16 g_Wgbf[4 * (size_t)G4H * 768];   // [4096][768] unit-major rows
__device__ __align__(16) __nv_bfloat16 g_Wrbf[4 * (size_t)PP * 3072];   // [256][3072]
__device__ __align__(16) __nv_bfloat16 g_hpbf[2][BB * 512];             // hp' [hi|lo], double-buffered
__device__ __align__(16) __nv_bfloat16 g_hbf[2][BB * 2048];             // h'  [hi|lo], double-buffered
__device__ float g_pp[2][8][BB][PP];                                    // proj split-K8 partials
// producer-consumer flags (one per 128B line)
__device__ unsigned g_fA[NBLK * 32];
__device__ unsigned g_fB[NBLK * 32];
__device__ unsigned g_fC[32 * 32];

// ---------------------------------------------------------------------------
// Helpers
// ---------------------------------------------------------------------------
__device__ __forceinline__ uint32_t smem_u32(const void* p) {
    uint32_t a;
    asm("{ .reg .u64 t; cvta.to.shared.u64 t, %1; cvt.u32.u64 %0, t; }" : "=r"(a) : "l"(p));
    return a;
}
__device__ __forceinline__ void cp_async16(uint32_t dst, const void* src) {
    asm volatile("cp.async.cg.shared.global [%0], [%1], 16;" :: "r"(dst), "l"(src));
}
__device__ __forceinline__ void cp_commit() {
    asm volatile("cp.async.commit_group;" ::: "memory");
}
template <int N>
__device__ __forceinline__ void cp_wait() {
    asm volatile("cp.async.wait_group %0;" :: "n"(N) : "memory");
}
__device__ __forceinline__ void ldm_x4(uint32_t addr, uint32_t& r0, uint32_t& r1,
                                       uint32_t& r2, uint32_t& r3) {
    asm volatile("ldmatrix.sync.aligned.m8n8.x4.shared.b16 {%0,%1,%2,%3}, [%4];"
                 : "=r"(r0), "=r"(r1), "=r"(r2), "=r"(r3) : "r"(addr));
}
__device__ __forceinline__ void ldm_x2(uint32_t addr, uint32_t& r0, uint32_t& r1) {
    asm volatile("ldmatrix.sync.aligned.m8n8.x2.shared.b16 {%0,%1}, [%2];"
                 : "=r"(r0), "=r"(r1) : "r"(addr));
}
__device__ __forceinline__ void mma16816(float* d, const uint32_t* a,
                                         uint32_t b0, uint32_t b1) {
    asm volatile(
        "mma.sync.aligned.m16n8k16.row.col.f32.bf16.bf16.f32 "
        "{%0,%1,%2,%3}, {%4,%5,%6,%7}, {%8,%9}, {%0,%1,%2,%3};"
        : "+f"(d[0]), "+f"(d[1]), "+f"(d[2]), "+f"(d[3])
        : "r"(a[0]), "r"(a[1]), "r"(a[2]), "r"(a[3]), "r"(b0), "r"(b1));
}
__device__ __forceinline__ unsigned ld_acq(const unsigned* p) {
    unsigned v;
    asm volatile("ld.acquire.gpu.global.u32 %0, [%1];" : "=r"(v) : "l"(p) : "memory");
    return v;
}
__device__ __forceinline__ void st_rel(unsigned* p, unsigned v) {
    asm volatile("st.release.gpu.global.u32 [%0], %1;" :: "l"(p), "r"(v) : "memory");
}
__device__ __forceinline__ void poll_ge(unsigned* f, unsigned p) {
    while (ld_acq(f) < p) { }
}

__global__ void reset_flags_kernel() {
    int i = threadIdx.x;
    if (i < NBLK) { g_fA[i * 32] = 0; g_fB[i * 32] = 0; }
    if (i < 32)   { g_fC[i * 32] = 0; }
}

// ---------------------------------------------------------------------------
// Conversions (unchanged)
// ---------------------------------------------------------------------------
__global__ void conv_A_kernel(const float* __restrict__ in, __nv_bfloat16* __restrict__ out,
                              int K, int remap) {
    int idx = blockIdx.x * 256 + threadIdx.x;
    if (idx >= MROWS * K) return;
    int m = idx / K;
    int k = idx - m * K;
    float a = in[idx];
    int r = remap ? (((m & 255) << 6) | (m >> 8)) : m;
    __nv_bfloat16 hi = __float2bfloat16(a);
    __nv_bfloat16 lo = __float2bfloat16(a - __bfloat162float(hi));
    size_t base = (size_t)r * (3 * K);
    out[base + k] = hi;
    out[base + K + k] = hi;
    out[base + 2 * K + k] = lo;
}

__global__ void conv_W_kernel(const float* __restrict__ in, __nv_bfloat16* __restrict__ out,
                              int K) {
    int idx = blockIdx.x * 256 + threadIdx.x;
    if (idx >= G4H * K) return;
    int n = idx / K;
    int k = idx - n * K;
    float a = in[idx];
    __nv_bfloat16 hi = __float2bfloat16(a);
    __nv_bfloat16 lo = __float2bfloat16(a - __bfloat162float(hi));
    int np = 4 * (n & 1023) + (n >> 10);
    size_t base = (size_t)np * (3 * K);
    out[base + k] = hi;
    out[base + K + k] = lo;
    out[base + 2 * K + k] = hi;
}

__global__ void conv_Whh_kernel(const float* __restrict__ in, __nv_bfloat16* __restrict__ out) {
    int idx = blockIdx.x * 256 + threadIdx.x;
    if (idx >= G4H * PP) return;
    int n = idx >> 8, k = idx & 255;
    float a = in[idx];
    __nv_bfloat16 hi = __float2bfloat16(a);
    __nv_bfloat16 lo = __float2bfloat16(a - __bfloat162float(hi));
    int np = 4 * (n & 1023) + (n >> 10);
    size_t base = (size_t)np * 768;
    out[base + k] = hi;          // [Whi | Wlo | Whi]
    out[base + 256 + k] = lo;
    out[base + 512 + k] = hi;
}
__global__ void conv_Whr_kernel(const float* __restrict__ in, __nv_bfloat16* __restrict__ out) {
    int idx = blockIdx.x * 256 + threadIdx.x;
    if (idx >= PP * HH) return;
    int n = idx >> 10, k = idx & 1023;
    float a = in[idx];
    __nv_bfloat16 hi = __float2bfloat16(a);
    __nv_bfloat16 lo = __float2bfloat16(a - __bfloat162float(hi));
    size_t base = (size_t)n * 3072;
    out[base + k] = hi;          // [Whi | Wlo | Whi]
    out[base + 1024 + k] = lo;
    out[base + 2048 + k] = hi;
}

// ---------------------------------------------------------------------------
// Input-projection GEMM via mma.sync (unchanged, passing since R9)
// ---------------------------------------------------------------------------
#define LDS_ROW 40
#define GTILE_BYTES (128 * LDS_ROW * 2)

__global__ __launch_bounds__(256) void gemm_mma_kernel(
    const __nv_bfloat16* __restrict__ A,
    const __nv_bfloat16* __restrict__ W,
    const float* __restrict__ b1, const float* __restrict__ b2,
    float* __restrict__ C, int K3)
{
    __shared__ alignas(16) __nv_bfloat16 sA[2][128][LDS_ROW];
    __shared__ alignas(16) __nv_bfloat16 sB[2][128][LDS_ROW];

    const int tid  = threadIdx.x;
    const int wid  = tid >> 5;
    const int lane = tid & 31;
    const int m0 = blockIdx.y * 128;
    const int n0 = blockIdx.x * 128;
    const int wm = (wid >> 2) * 64;
    const int wn = (wid & 3) * 32;

    const uint32_t sA_u = smem_u32(sA);
    const uint32_t sB_u = smem_u32(sB);

    float acc[4][4][4];
#pragma unroll
    for (int mi = 0; mi < 4; mi++)
#pragma unroll
        for (int nj = 0; nj < 4; nj++)
#pragma unroll
            for (int e = 0; e < 4; e++) acc[mi][nj][e] = 0.f;

    const int nchunks = K3 >> 5;

    const uint32_t a_off = (uint32_t)((wm + (lane & 15)) * LDS_ROW + ((lane >> 4) * 8)) * 2;
    const uint32_t b_off = (uint32_t)((wn + ((lane >> 3) & 1) * 8 + (lane & 7)) * LDS_ROW
                                      + ((lane >> 4) * 8)) * 2;

    {
        const __nv_bfloat16* Ag = A + (size_t)m0 * K3;
        const __nv_bfloat16* Wg = W + (size_t)n0 * K3;
#pragma unroll
        for (int i = 0; i < 2; i++) {
            int seg = i * 256 + tid;
            int row = seg >> 2, s = seg & 3;
            uint32_t off = (uint32_t)(row * LDS_ROW + s * 8) * 2;
            cp_async16(sA_u + off, Ag + (size_t)row * K3 + s * 8);
            cp_async16(sB_u + off, Wg + (size_t)row * K3 + s * 8);
        }
        cp_commit();
    }

    for (int c = 0; c < nchunks; c++) {
        const int buf = c & 1;
        if (c + 1 < nchunks) {
            const int nb = (c + 1) & 1;
            const __nv_bfloat16* Ag = A + (size_t)m0 * K3 + (c + 1) * 32;
            const __nv_bfloat16* Wg = W + (size_t)n0 * K3 + (c + 1) * 32;
#pragma unroll
            for (int i = 0; i < 2; i++) {
                int seg = i * 256 + tid;
                int row = seg >> 2, s = seg & 3;
                uint32_t off = (uint32_t)(nb * GTILE_BYTES + (row * LDS_ROW + s * 8) * 2);
                cp_async16(sA_u + off, Ag + (size_t)row * K3 + s * 8);
                cp_async16(sB_u + off, Wg + (size_t)row * K3 + s * 8);
            }
            cp_commit();
            cp_wait<1>();
        } else {
            cp_wait<0>();
        }
        __syncthreads();

        const uint32_t abase = sA_u + buf * GTILE_BYTES;
        const uint32_t bbase = sB_u + buf * GTILE_BYTES;
#pragma unroll
        for (int ks = 0; ks < 2; ks++) {
            const uint32_t koff = (uint32_t)(ks * 16 * 2);
            uint32_t a[4][4];
#pragma unroll
            for (int mi = 0; mi < 4; mi++)
                ldm_x4(abase + a_off + koff + (uint32_t)(mi * 16 * LDS_ROW * 2),
                       a[mi][0], a[mi][1], a[mi][2], a[mi][3]);
            uint32_t bfrag[4][2];
#pragma unroll
            for (int g = 0; g < 2; g++) {
                uint32_t r0, r1, r2, r3;
                ldm_x4(bbase + b_off + koff + (uint32_t)(g * 16 * LDS_ROW * 2),
                       r0, r1, r2, r3);
                bfrag[g * 2 + 0][0] = r0; bfrag[g * 2 + 0][1] = r2;
                bfrag[g * 2 + 1][0] = r1; bfrag[g * 2 + 1][1] = r3;
            }
#pragma unroll
            for (int mi = 0; mi < 4; mi++)
#pragma unroll
                for (int nj = 0; nj < 4; nj++)
                    mma16816(acc[mi][nj], a[mi], bfrag[nj][0], bfrag[nj][1]);
        }
        __syncthreads();
    }

    float bs0[4], bs1[4];
#pragma unroll
    for (int nj = 0; nj < 4; nj++) {
        int n = n0 + wn + nj * 8 + (lane & 3) * 2;
        int o0 = ((n & 3) << 10) | (n >> 2);
        int o1 = (((n + 1) & 3) << 10) | ((n + 1) >> 2);
        bs0[nj] = b1[o0] + b2[o0];
        bs1[nj] = b1[o1] + b2[o1];
    }
#pragma unroll
    for (int mi = 0; mi < 4; mi++) {
        int mrow = m0 + wm + mi * 16 + (lane >> 2);
#pragma unroll
        for (int nj = 0; nj < 4; nj++) {
            int n = n0 + wn + nj * 8 + (lane & 3) * 2;
            float2 v0 = make_float2(acc[mi][nj][0] + bs0[nj], acc[mi][nj][1] + bs1[nj]);
            float2 v1 = make_float2(acc[mi][nj][2] + bs0[nj], acc[mi][nj][3] + bs1[nj]);
            *(float2*)&C[(size_t)mrow * G4H + n]       = v0;
            *(float2*)&C[(size_t)(mrow + 8) * G4H + n] = v1;
        }
    }
}

// ---------------------------------------------------------------------------
// Tensor-core persistent LSTM scan, v5.
// Gate: two-stage fC poll overlapped with chunk loads; passes grouped by
//       K-part (slots hi0,lo0 then hi1,lo1).
// Proj: split-K8 — warp-groups 0/1 each take half the quarter's K (3 passes),
//       partials -> g_pp[par][q*2+grp]. Reduce sums 8.
// Flags via ld.acquire / st.release (no __threadfence).
// ---------------------------------------------------------------------------
#define CH_ROW   136
#define CH_BYTES (64 * CH_ROW * 2)     // 17408

#define OFF_WG 0
#define SZ_WG  (32 * 776 * 2)          // 49664
#define OFF_WR (OFF_WG + SZ_WG)
#define SZ_WR  (8 * 3080 * 2)          // 49280
#define OFF_ST (OFF_WR + SZ_WR)
#define SZ_ST  (4 * CH_BYTES)          // 69632
#define OFF_SH (OFF_ST + SZ_ST)
#define SZ_SH  (64 * 9 * 4)            // 2304
#define OFF_XG (OFF_SH + SZ_SH)
#define SZ_XG  (2 * 64 * 36 * 4)       // 18432
#define SCAN_SMEM (OFF_XG + SZ_XG)     // 189312

__global__ __launch_bounds__(256, 1) void lstm_scan_tc(
    const float* __restrict__ xg,
    const __nv_bfloat16* __restrict__ Wg,
    const __nv_bfloat16* __restrict__ Wr,
    float* __restrict__ hp_out,
    unsigned pbase)
{
    extern __shared__ char dsm[];
    float* sH = (float*)(dsm + OFF_SH);
    float* sXg = (float*)(dsm + OFF_XG);
    const uint32_t sWg_u = smem_u32(dsm + OFF_WG);
    const uint32_t sWr_u = smem_u32(dsm + OFF_WR);
    const uint32_t st_u  = smem_u32(dsm + OFF_ST);
    const uint32_t sXg_u = smem_u32(dsm + OFF_XG);

    const int tid = threadIdx.x;
    const int lane = tid & 31;
    const int w = tid >> 5;
    const int j = blockIdx.x;
    const int g = j & 31;
    const int q = j >> 5;
    const int wq = q * 256;
    const int wm = (w & 3) * 16;
    const int wn = (w >> 2) * 16;
    const int grp = w >> 2;          // proj warp-group (K-half)

    // persistent weight slices + xg(0)
    for (int i = tid; i < 3072; i += 256) {            // Wg: 32 rows x 96 segs
        int r = i / 96, s = i % 96;
        cp_async16(sWg_u + (uint32_t)(r * 776 + s * 8) * 2,
                   Wg + (size_t)(j * 32 + r) * 768 + s * 8);
    }
    for (int i = tid; i < 3072; i += 256) {            // Wr: 8 rows x 384 segs
        int r = i / 384, s = i % 384;
        cp_async16(sWr_u + (uint32_t)(r * 3080 + s * 8) * 2,
                   Wr + (size_t)(g * 8 + r) * 3072 + s * 8);
    }
    for (int k = 0; k < 2; k++) {
        int i = k * 256 + tid;
        int r = i >> 3, s = i & 7;
        cp_async16(sXg_u + (uint32_t)(r * 144 + s * 16),
                   xg + (size_t)r * G4H + j * 32 + s * 4);
    }
    cp_commit();
    cp_wait<0>();
    __syncthreads();

    float cst[4] = {0.f, 0.f, 0.f, 0.f};

    for (int t = 0; t < TT; t++) {
        const int par = t & 1;
        float acc[2][4];
#pragma unroll
        for (int nj = 0; nj < 2; nj++)
#pragma unroll
            for (int e = 0; e < 4; e++) acc[nj][e] = 0.f;

        // ================= gate phase =================
        if (t > 0) {
            const __nv_bfloat16* hp = g_hpbf[(t - 1) & 1];
            // stage 1: lower-half producers -> chunks hi0 (slot0), lo0 (slot1)
            if (tid < 16) poll_ge(&g_fC[tid * 32], pbase + t);
            __syncthreads();
#pragma unroll
            for (int a = 0; a < 2; a++) {               // a=0: hi0 (col 0), a=1: lo0 (col 256)
                int ccol = a * 256;
#pragma unroll
                for (int k = 0; k < 4; k++) {
                    int i = k * 256 + tid;
                    int r = i >> 4, s = i & 15;
                    cp_async16(st_u + (uint32_t)(a * CH_BYTES + (r * CH_ROW + s * 8) * 2),
                               hp + (size_t)r * 512 + ccol + s * 8);
                }
                cp_commit();
            }
            // stage 2: upper-half producers -> chunks hi1 (slot2), lo1 (slot3)
            if (tid < 16) poll_ge(&g_fC[(16 + tid) * 32], pbase + t);
            __syncthreads();
#pragma unroll
            for (int a = 0; a < 2; a++) {               // a=0: hi1 (col 128), a=1: lo1 (col 384)
                int ccol = 128 + a * 256;
#pragma unroll
                for (int k = 0; k < 4; k++) {
                    int i = k * 256 + tid;
                    int r = i >> 4, s = i & 15;
                    cp_async16(st_u + (uint32_t)((2 + a) * CH_BYTES + (r * CH_ROW + s * 8) * 2),
                               hp + (size_t)r * 512 + ccol + s * 8);
                }
                cp_commit();
            }
            // K-part0: slots {0,0,1}, W cols {0,256,512}
            cp_wait<2>();
            __syncthreads();
            {
                const int asl[3] = {0, 0, 1};
                const int wbs[3] = {0, 256, 512};
#pragma unroll
                for (int p = 0; p < 3; p++) {
                    const uint32_t abase = st_u + (uint32_t)(asl[p] * CH_BYTES);
                    const int wb = wbs[p];
#pragma unroll
                    for (int ks = 0; ks < 8; ks++) {
                        uint32_t a[4], r0, r1, r2, r3;
                        ldm_x4(abase + (uint32_t)((wm + (lane & 15)) * CH_ROW
                                                  + (lane >> 4) * 8 + ks * 16) * 2,
                               a[0], a[1], a[2], a[3]);
                        ldm_x4(sWg_u + (uint32_t)((wn + ((lane >> 3) & 1) * 8 + (lane & 7)) * 776
                                                  + (lane >> 4) * 8 + wb + ks * 16) * 2,
                               r0, r1, r2, r3);
                        mma16816(acc[0], a, r0, r2);
                        mma16816(acc[1], a, r1, r3);
                    }
                }
            }
            // K-part1: slots {2,2,3}, W cols {128,384,640}
            cp_wait<0>();
            __syncthreads();
            {
                const int asl[3] = {2, 2, 3};
                const int wbs[3] = {128, 384, 640};
#pragma unroll
                for (int p = 0; p < 3; p++) {
                    const uint32_t abase = st_u + (uint32_t)(asl[p] * CH_BYTES);
                    const int wb = wbs[p];
#pragma unroll
                    for (int ks = 0; ks < 8; ks++) {
                        uint32_t a[4], r0, r1, r2, r3;
                        ldm_x4(abase + (uint32_t)((wm + (lane & 15)) * CH_ROW
                                                  + (lane >> 4) * 8 + ks * 16) * 2,
                               a[0], a[1], a[2], a[3]);
                        ldm_x4(sWg_u + (uint32_t)((wn + ((lane >> 3) & 1) * 8 + (lane & 7)) * 776
                                                  + (lane >> 4) * 8 + wb + ks * 16) * 2,
                               r0, r1, r2, r3);
                        mma16816(acc[0], a, r0, r2);
                        mma16816(acc[1], a, r1, r3);
                    }
                }
            }
        }

        // ---- add xg (SMEM buf t&1), cell update ----
        {
            const float* sx = sXg + par * (64 * 36);
            int rbase = wm + (lane >> 2);
#pragma unroll
            for (int nj = 0; nj < 2; nj++) {
#pragma unroll
                for (int rp = 0; rp < 2; rp++) {
                    int row = rbase + rp * 8;
                    int cl = wn + nj * 8 + (lane & 3) * 2;
                    float2 xv = *(const float2*)&sx[row * 36 + cl];
                    float x0 = acc[nj][rp * 2 + 0] + xv.x;
                    float x1 = acc[nj][rp * 2 + 1] + xv.y;
                    float y0 = __shfl_xor_sync(0xffffffffu, x0, 1);
                    float y1 = __shfl_xor_sync(0xffffffffu, x1, 1);
                    if (!(lane & 1)) {
                        float gi = 1.f / (1.f + __expf(-x0));
                        float gf = 1.f / (1.f + __expf(-x1));
                        float gg = tanhf(y0);
                        float go = 1.f / (1.f + __expf(-y1));
                        float c = gf * cst[nj * 2 + rp] + gi * gg;
                        cst[nj * 2 + rp] = c;
                        float h = go * tanhf(c);
                        sH[row * 9 + (cl >> 2)] = h;
                    }
                }
            }
        }
        __syncthreads();

        // ---- h'(t) writeback ----
        if (tid < 64) {
            __align__(16) __nv_bfloat16 hi8[8], lo8[8];
#pragma unroll
            for (int u = 0; u < 8; u++) {
                float hv = sH[tid * 9 + u];
                hi8[u] = __float2bfloat16(hv);
                lo8[u] = __float2bfloat16(hv - __bfloat162float(hi8[u]));
            }
            __nv_bfloat16* dst = g_hbf[par] + (size_t)tid * 2048 + j * 8;
            __stcg((uint4*)dst,          *(const uint4*)hi8);
            __stcg((uint4*)(dst + 1024), *(const uint4*)lo8);
        }
        __syncthreads();
        if (tid == 0) st_rel(&g_fA[j * 32], pbase + t + 1);

        // ================= projection phase (split-K8) =================
        {
            if (tid < 32) poll_ge(&g_fA[(q * 32 + tid) * 32], pbase + t + 1);
            __syncthreads();

            const __nv_bfloat16* hb = g_hbf[par];
            // chunks: slot0=hi0(wq), slot1=hi1(wq+128), slot2=lo0(1024+wq), slot3=lo1(1024+wq+128)
            const int cb[4] = {wq, wq + 128, 1024 + wq, 1024 + wq + 128};
            // bundle xg(t+1) prefetch with chunk 0's group
            if (t + 1 < TT) {
#pragma unroll
                for (int k = 0; k < 2; k++) {
                    int i = k * 256 + tid;
                    int r = i >> 3, s = i & 7;
                    cp_async16(sXg_u + (uint32_t)(((t + 1) & 1) * (64 * 144) + r * 144 + s * 16),
                               xg + (size_t)((t + 1) * 64 + r) * G4H + j * 32 + s * 4);
                }
            }
#pragma unroll
            for (int a = 0; a < 4; a++) {
#pragma unroll
                for (int k = 0; k < 4; k++) {
                    int i = k * 256 + tid;
                    int r = i >> 4, s = i & 15;
                    cp_async16(st_u + (uint32_t)(a * CH_BYTES + (r * CH_ROW + s * 8) * 2),
                               hb + (size_t)r * 2048 + cb[a] + s * 8);
                }
                cp_commit();
            }

            float accP[4] = {0.f, 0.f, 0.f, 0.f};
            const int wq2 = wq + grp * 128;
            const int ahi = grp;         // slot for A-hi half
            const int alo = 2 + grp;     // slot for A-lo half
            // passes after hi chunks ready: (ahi, wq2), (ahi, 1024+wq2)
            cp_wait<2>();
            __syncthreads();
#pragma unroll
            for (int p = 0; p < 2; p++) {
                const uint32_t abase = st_u + (uint32_t)(ahi * CH_BYTES);
                const int wb = (p == 0) ? wq2 : (1024 + wq2);
#pragma unroll
                for (int ks = 0; ks < 8; ks++) {
                    uint32_t a[4], b0, b1;
                    ldm_x4(abase + (uint32_t)((wm + (lane & 15)) * CH_ROW
                                              + (lane >> 4) * 8 + ks * 16) * 2,
                           a[0], a[1], a[2], a[3]);
                    ldm_x2(sWr_u + (uint32_t)((lane & 7) * 3080 + ((lane >> 3) & 1) * 8
                                              + wb + ks * 16) * 2,
                           b0, b1);
                    mma16816(accP, a, b0, b1);
                }
            }
            // pass after lo chunks: (alo, 2048+wq2)
            cp_wait<0>();
            __syncthreads();
            {
                const uint32_t abase = st_u + (uint32_t)(alo * CH_BYTES);
                const int wb = 2048 + wq2;
#pragma unroll
                for (int ks = 0; ks < 8; ks++) {
                    uint32_t a[4], b0, b1;
                    ldm_x4(abase + (uint32_t)((wm + (lane & 15)) * CH_ROW
                                              + (lane >> 4) * 8 + ks * 16) * 2,
                           a[0], a[1], a[2], a[3]);
                    ldm_x2(sWr_u + (uint32_t)((lane & 7) * 3080 + ((lane >> 3) & 1) * 8
                                              + wb + ks * 16) * 2,
                           b0, b1);
                    mma16816(accP, a, b0, b1);
                }
            }
            // write partial (eighth e = q*2 + grp)
            {
                int row = wm + (lane >> 2);
                int col = g * 8 + (lane & 3) * 2;
                float* pp = &g_pp[par][q * 2 + grp][0][0];
                *(float2*)&pp[row * 256 + col]       = make_float2(accP[0], accP[1]);
                *(float2*)&pp[(row + 8) * 256 + col] = make_float2(accP[2], accP[3]);
            }
        }
        __syncthreads();
        if (tid == 0) st_rel(&g_fB[j * 32], pbase + t + 1);

        // ================= reduce (blocks j<32 only) =================
        if (j < 32) {
            if (tid < 4) poll_ge(&g_fB[(j + tid * 32) * 32], pbase + t + 1);
            __syncthreads();

            int r = tid >> 2;              // 0..63
            int c2 = (tid & 3) * 2;
            int col = j * 8 + c2;
            float sx = 0.f, sy = 0.f;
#pragma unroll
            for (int e = 0; e < 8; e++) {
                float2 s = *(const float2*)&g_pp[par][e][r][col];
                sx += s.x; sy += s.y;
            }

            __nv_bfloat16 hx = __float2bfloat16(sx);
            __nv_bfloat16 hy = __float2bfloat16(sy);
            __nv_bfloat16 lx = __float2bfloat16(sx - __bfloat162float(hx));
            __nv_bfloat16 ly = __float2bfloat16(sy - __bfloat162float(hy));
            __nv_bfloat162 hp2; hp2.x = hx; hp2.y = hy;
            __nv_bfloat162 lp2; lp2.x = lx; lp2.y = ly;
            __nv_bfloat16* hpb = g_hpbf[par];
            __stcg((uint32_t*)&hpb[r * 512 + col],       *(uint32_t*)&hp2);
            __stcg((uint32_t*)&hpb[r * 512 + 256 + col], *(uint32_t*)&lp2);

            __syncthreads();
            if (tid == 0) st_rel(&g_fC[j * 32], pbase + t + 1);

            // layer-output store off the critical path
            __stcg((float2*)&hp_out[((size_t)t * 64 + r) * PP + col],
                   make_float2(sx, sy));
        }
    }
}

// ---------------------------------------------------------------------------
// Launch
// ---------------------------------------------------------------------------
extern "C" void kernel_launch(void* const* d_in, const int* in_sizes, int n_in,
                              void* d_out, int out_size)
{
    const float* x     = (const float*)d_in[0];
    const float* W_ih0 = (const float*)d_in[1];
    const float* W_hh0 = (const float*)d_in[2];
    const float* b_ih0 = (const float*)d_in[3];
    const float* b_hh0 = (const float*)d_in[4];
    const float* W_hr0 = (const float*)d_in[5];
    const float* W_ihs = (const float*)d_in[6];
    const float* W_hhs = (const float*)d_in[7];
    const float* b_ihs = (const float*)d_in[8];
    const float* b_hhs = (const float*)d_in[9];
    const float* W_hrs = (const float*)d_in[10];

    float *xg, *hp;
    __nv_bfloat16 *Abf, *Wbf, *Wgbf, *Wrbf;
    cudaGetSymbolAddress((void**)&xg,   g_xg);
    cudaGetSymbolAddress((void**)&hp,   g_hp);
    cudaGetSymbolAddress((void**)&Abf,  g_Abf);
    cudaGetSymbolAddress((void**)&Wbf,  g_Wbf);
    cudaGetSymbolAddress((void**)&Wgbf, g_Wgbf);
    cudaGetSymbolAddress((void**)&Wrbf, g_Wrbf);

    cudaFuncSetAttribute(lstm_scan_tc,
                         cudaFuncAttributeMaxDynamicSharedMemorySize, SCAN_SMEM);

    dim3 ggrid(32, 128);   // N/128, M/128

    reset_flags_kernel<<<1, 256>>>();

    // scan weight conversions (all layers)
    conv_Whh_kernel<<<(G4H * PP) / 256, 256>>>(W_hh0, Wgbf);
    conv_Whr_kernel<<<(PP * HH) / 256, 256>>>(W_hr0, Wrbf);
    for (int l = 0; l < 3; l++) {
        conv_Whh_kernel<<<(G4H * PP) / 256, 256>>>(
            W_hhs + (size_t)l * G4H * PP, Wgbf + (size_t)(l + 1) * G4H * 768);
        conv_Whr_kernel<<<(PP * HH) / 256, 256>>>(
            W_hrs + (size_t)l * PP * HH, Wrbf + (size_t)(l + 1) * PP * 3072);
    }

    // ---- layer 0 ----
    conv_W_kernel<<<(G4H * DIN) / 256, 256>>>(W_ih0, Wbf, DIN);
    conv_A_kernel<<<(MROWS * DIN) / 256, 256>>>(x, Abf, DIN, 1);
    gemm_mma_kernel<<<ggrid, 256>>>(Abf, Wbf, b_ih0, b_hh0, xg, 3 * DIN);
    lstm_scan_tc<<<NBLK, 256, SCAN_SMEM>>>(xg, Wgbf, Wrbf, hp, 0u);

    // ---- layers 1..3 ----
    for (int l = 0; l < 3; l++) {
        conv_W_kernel<<<(G4H * PP) / 256, 256>>>(W_ihs + (size_t)l * G4H * PP, Wbf, PP);
        conv_A_kernel<<<(MROWS * PP) / 256, 256>>>(hp, Abf, PP, 0);
        gemm_mma_kernel<<<ggrid, 256>>>(Abf, Wbf,
                                        b_ihs + (size_t)l * G4H,
                                        b_hhs + (size_t)l * G4H,
                                        xg, 3 * PP);
        lstm_scan_tc<<<NBLK, 256, SCAN_SMEM>>>(xg,
                                               Wgbf + (size_t)(l + 1) * G4H * 768,
                                               Wrbf + (size_t)(l + 1) * PP * 3072,
                                               hp, (unsigned)((l + 1) * TT));
    }

    // output = hp of last timestep, last layer
    cudaMemcpyAsync(d_out, hp + (size_t)(TT - 1) * BB * PP,
                    (size_t)BB * PP * sizeof(float),
                    cudaMemcpyDeviceToDevice);
    (void)in_sizes; (void)n_in; (void)out_size;
}